// round 15
// baseline (speedup 1.0000x reference)
#include <cuda_runtime.h>
#include <math.h>
#include <stdint.h>

// ---------------- problem constants ----------------
#define HWN    20736               // 144*144
#define NB     4
#define DDIM   300
#define KPAD   320                 // K padded for BK=16 pipeline
#define PLANE  (DDIM*HWN)          // 6,220,800  (Y6 row stride region)
#define PLANEP (KPAD*HWN)          // 6,635,520  (padded activation plane)
#define HW2    20164               // 142*142
#define ECH    64                  // encoder channels padded 21 -> 64

// ---------------- static device scratch ----------------
__device__ float g_Y6 [(size_t)NB*6*PLANE];
__device__ float g_C12[(size_t)NB*PLANEP];
__device__ float g_X12[(size_t)NB*PLANEP];
__device__ float g_XT1[(size_t)NB*PLANEP];
__device__ float g_CT1[(size_t)NB*PLANEP];
__device__ float g_G0 [(size_t)NB*PLANEP];
__device__ float g_G1 [(size_t)NB*PLANEP];
__device__ float g_Ypad[(size_t)NB*ECH*HWN];    // y zero-padded 21->64 channels
__device__ float g_WtD[6*KPAD*KPAD];            // 6 D weights, [g][k<320][m<320], zero pads
__device__ float g_WtE[ECH*1856];               // stacked encoder weights, transposed, zero pads
__device__ float g_bE [1856];
__device__ float g_Wc [2700*128];               // conv weights [(c*9+tap)][o]
__device__ float g_Wt2[128*128];                // line_w2 transposed
__device__ float g_h1[(size_t)NB*128*HW2];
__device__ float g_h2[(size_t)NB*128*HW2];

// ---------------- helpers ----------------
__device__ __forceinline__ float gelu_f(float x) {
    return 0.5f * x * (1.0f + erff(x * 0.7071067811865475f));
}
__device__ __forceinline__ float sigm(float x) { return 1.0f / (1.0f + expf(-x)); }

__device__ __forceinline__ unsigned long long dup2(float x) {
    unsigned long long r;
    asm("mov.b64 %0, {%1, %1};" : "=l"(r) : "f"(x));
    return r;
}
__device__ __forceinline__ void fma2(unsigned long long &d, unsigned long long a, unsigned long long b) {
    asm("fma.rn.f32x2 %0, %1, %2, %0;" : "+l"(d) : "l"(a), "l"(b));
}
__device__ __forceinline__ float2 unp(unsigned long long v) {
    float2 r;
    asm("mov.b64 {%0, %1}, %2;" : "=f"(r.x), "=f"(r.y) : "l"(v));
    return r;
}

#define CP_COMMIT()  asm volatile("cp.async.commit_group;" ::: "memory")
#define CP_WAIT(n)   asm volatile("cp.async.wait_group %0;" :: "n"(n) : "memory")

__device__ __forceinline__ void cpa16(uint32_t dst, const float* src) {
    asm volatile("cp.async.ca.shared.global [%0], [%1], 16;" :: "r"(dst), "l"(src) : "memory");
}
__device__ __forceinline__ void cpa4(uint32_t dst, const float* src) {
    asm volatile("cp.async.ca.shared.global [%0], [%1], 4;" :: "r"(dst), "l"(src) : "memory");
}
__device__ __forceinline__ void sts0(uint32_t dst) {
    asm volatile("st.shared.u32 [%0], %1;" :: "r"(dst), "r"(0u) : "memory");
}

// ---------------- cp.async stage loader ----------------
// A tile: BK x TM from Wt (K padded: no k predicate, Mpad covers m range).
// X tile: BK x 128 from Xb (predicated on N only; K padded rows exist in buffers).
template<int BK, int TM>
__device__ __forceinline__ void stage_issue(
    uint32_t sA, uint32_t sX,
    const float* __restrict__ Wt, const float* __restrict__ Xb,
    int k0, int m0, int p0, int Mpad, int N)
{
    const int tid = threadIdx.x;
    constexpr int ACH = BK * TM / 1024;     // 16B chunks per thread
#pragma unroll
    for (int i = 0; i < ACH; i++) {
        int off = (tid + i * 256) * 4;
        int kk = off / TM, mm = off % TM;
        cpa16(sA + off * 4, Wt + (size_t)(k0 + kk) * Mpad + m0 + mm);
    }
    constexpr int XCH = BK * 128 / 1024;
#pragma unroll
    for (int i = 0; i < XCH; i++) {
        int off = (tid + i * 256) * 4;
        int kk = off >> 7, pp = p0 + (off & 127);
        const float* src = Xb + (size_t)(k0 + kk) * N + pp;
        uint32_t dst = sX + off * 4;
        if (pp + 3 < N) {
            cpa16(dst, src);
        } else {
#pragma unroll
            for (int e = 0; e < 4; e++) {
                if (pp + e < N) cpa4(dst + e * 4, src + e);
                else            sts0(dst + e * 4);
            }
        }
    }
}

// ---------------- GEMM body: 128-wide N tile, TM = 16*MT wide M tile ----------------
// MODE 0: O = gelu(acc + bias)
// MODE 1: fused gate combine (this GEMM is the 'wix' gate):
//   gi=gelu(acc+bias); it=sigm(gi+Yi); ft=sigm(G1+Yf); ctl=Ya+S2-G0;
//   ct=S1*ft+ctl*it; O=ct; O2=relu(ct)
template<int MODE, int BK, int MT>
__device__ __forceinline__ void gemm_body(
    const float* __restrict__ Wt, const float* __restrict__ bias,
    const float* __restrict__ X, float* O,
    int K, int M, int Mpad, int N, size_t bsX, size_t bsO,
    const float* __restrict__ G0p, const float* __restrict__ G1p,
    const float* __restrict__ Ya, const float* __restrict__ Yf, const float* __restrict__ Yi,
    size_t bsY, const float* __restrict__ S1, const float* __restrict__ S2, float* O2,
    float* AsBuf, float* XsBuf, int m0)
{
    constexpr int TM = 16 * MT;
    constexpr int MP = MT / 2;
    constexpr int STG = BK * 128;           // floats per stage buffer
    const int tid = threadIdx.x;
    const int tx = tid & 15, ty = tid >> 4;
    const int p0 = blockIdx.x * 128;
    const int b  = blockIdx.z;
    const float* Xb = X + (size_t)b * bsX;

    uint32_t aAddr = (uint32_t)__cvta_generic_to_shared(AsBuf);
    uint32_t xAddr = (uint32_t)__cvta_generic_to_shared(XsBuf);

    unsigned long long acc2[MP][8];
#pragma unroll
    for (int i = 0; i < MP; i++)
#pragma unroll
        for (int j = 0; j < 8; j++) acc2[i][j] = 0ull;

    stage_issue<BK, TM>(aAddr, xAddr, Wt, Xb, 0, m0, p0, Mpad, N);
    CP_COMMIT();

    int buf = 0;
    for (int k0 = 0; k0 < K; k0 += BK) {
        if (k0 + BK < K) {
            int nb = buf ^ 1;
            stage_issue<BK, TM>(aAddr + nb * STG * 4, xAddr + nb * STG * 4,
                                Wt, Xb, k0 + BK, m0, p0, Mpad, N);
            CP_COMMIT();
            CP_WAIT(1);
        } else {
            CP_WAIT(0);
        }
        __syncthreads();
        const float* As = AsBuf + buf * STG;
        const float* Xs = XsBuf + buf * STG;
#pragma unroll
        for (int kk = 0; kk < BK; kk++) {
            unsigned long long a2[MP];
            const float* ab = As + kk * TM + ty * MT;
            if (MT == 8) {
                ulonglong2 v0 = *(const ulonglong2*)ab;
                ulonglong2 v1 = *(const ulonglong2*)(ab + 4);
                a2[0] = v0.x; a2[1] = v0.y;
                if (MP > 2) { a2[2] = v1.x; a2[3] = v1.y; }
            } else {
                ulonglong2 v0 = *(const ulonglong2*)ab;
                a2[0] = v0.x; a2[1] = v0.y;
            }
            float4 xa = *(const float4*)(Xs + kk * 128 + tx * 4);
            float4 xb = *(const float4*)(Xs + kk * 128 + 64 + tx * 4);
            unsigned long long xd[8] = {dup2(xa.x), dup2(xa.y), dup2(xa.z), dup2(xa.w),
                                        dup2(xb.x), dup2(xb.y), dup2(xb.z), dup2(xb.w)};
#pragma unroll
            for (int ip = 0; ip < MP; ip++)
#pragma unroll
                for (int j = 0; j < 8; j++) fma2(acc2[ip][j], a2[ip], xd[j]);
        }
        __syncthreads();
        buf ^= 1;
    }

    const int pA = p0 + tx * 4;
    const int pB = p0 + 64 + tx * 4;

    if (MODE == 0) {
#pragma unroll
        for (int ip = 0; ip < MP; ip++) {
            float2 v[8];
#pragma unroll
            for (int j = 0; j < 8; j++) v[j] = unp(acc2[ip][j]);
#pragma unroll
            for (int h = 0; h < 2; h++) {
                int o = m0 + ty * MT + 2 * ip + h;
                if (o >= M) continue;
                float bv = bias[o];
                size_t row = (size_t)b * bsO + (size_t)o * N;
                float r[8];
#pragma unroll
                for (int j = 0; j < 8; j++) r[j] = gelu_f((h ? v[j].y : v[j].x) + bv);
                if (pA + 3 < N) {
                    float4 st; st.x = r[0]; st.y = r[1]; st.z = r[2]; st.w = r[3];
                    *(float4*)(O + row + pA) = st;
                } else {
#pragma unroll
                    for (int e = 0; e < 4; e++) if (pA + e < N) O[row + pA + e] = r[e];
                }
                if (pB + 3 < N) {
                    float4 st; st.x = r[4]; st.y = r[5]; st.z = r[6]; st.w = r[7];
                    *(float4*)(O + row + pB) = st;
                } else {
#pragma unroll
                    for (int e = 0; e < 4; e++) if (pB + e < N) O[row + pB + e] = r[4 + e];
                }
            }
        }
    } else {
        // only used with N multiple of 128 (full tiles)
#pragma unroll
        for (int ip = 0; ip < MP; ip++) {
            float2 v[8];
#pragma unroll
            for (int j = 0; j < 8; j++) v[j] = unp(acc2[ip][j]);
#pragma unroll
            for (int h = 0; h < 2; h++) {
                int o = m0 + ty * MT + 2 * ip + h;
                if (o >= M) continue;
                float bv = bias[o];
                size_t rO = (size_t)b * bsO + (size_t)o * N;
                size_t rY = (size_t)b * bsY + (size_t)o * N;
#pragma unroll
                for (int g = 0; g < 2; g++) {
                    int pc = g ? pB : pA;
                    float G0a[4], G1a[4], YAa[4], YFa[4], YIa[4], S1a[4], S2a[4];
                    *(float4*)G0a = *(const float4*)(G0p + rO + pc);
                    *(float4*)G1a = *(const float4*)(G1p + rO + pc);
                    *(float4*)YAa = *(const float4*)(Ya + rY + pc);
                    *(float4*)YFa = *(const float4*)(Yf + rY + pc);
                    *(float4*)YIa = *(const float4*)(Yi + rY + pc);
                    *(float4*)S1a = *(const float4*)(S1 + rO + pc);
                    if (S2) { *(float4*)S2a = *(const float4*)(S2 + rO + pc); }
                    else    { S2a[0] = S2a[1] = S2a[2] = S2a[3] = 0.f; }
                    float ct[4], xt[4];
#pragma unroll
                    for (int j = 0; j < 4; j++) {
                        float accv = h ? v[4 * g + j].y : v[4 * g + j].x;
                        float gi  = gelu_f(accv + bv);
                        float it  = sigm(gi + YIa[j]);
                        float ft  = sigm(G1a[j] + YFa[j]);
                        float ctl = YAa[j] + S2a[j] - G0a[j];
                        ct[j] = S1a[j] * ft + ctl * it;
                        xt[j] = fmaxf(ct[j], 0.f);
                    }
                    float4 c4; c4.x = ct[0]; c4.y = ct[1]; c4.z = ct[2]; c4.w = ct[3];
                    float4 x4; x4.x = xt[0]; x4.y = xt[1]; x4.z = xt[2]; x4.w = xt[3];
                    *(float4*)(O  + rO + pc) = c4;
                    *(float4*)(O2 + rO + pc) = x4;
                }
            }
        }
    }
}

template<int MODE, int BK>
__global__ void __launch_bounds__(256, 2) gemm_tile(
    const float* __restrict__ Wt, const float* __restrict__ bias,
    const float* __restrict__ X, float* O,
    int K, int M, int Mpad, int N, size_t bsX, size_t bsO, int nFull,
    const float* G0p, const float* G1p,
    const float* Ya, const float* Yf, const float* Yi, size_t bsY,
    const float* S1, const float* S2, float* O2)
{
    __shared__ __align__(16) float As[2 * BK * 128];
    __shared__ __align__(16) float Xs[2 * BK * 128];
    if ((int)blockIdx.y < nFull)
        gemm_body<MODE, BK, 8>(Wt, bias, X, O, K, M, Mpad, N, bsX, bsO,
                               G0p, G1p, Ya, Yf, Yi, bsY, S1, S2, O2,
                               As, Xs, (int)blockIdx.y * 128);
    else
        gemm_body<MODE, BK, 4>(Wt, bias, X, O, K, M, Mpad, N, bsX, bsO,
                               G0p, G1p, Ya, Yf, Yi, bsY, S1, S2, O2,
                               As, Xs, nFull * 128 + ((int)blockIdx.y - nFull) * 64);
}

// ---------------- 3x3 valid conv 300->128, + gelu (f32x2) ----------------
__global__ void __launch_bounds__(256) conv3(const float* __restrict__ Xin,
                                             const float* __restrict__ bias,
                                             float* __restrict__ H1)
{
    __shared__ __align__(16) float Ws[10 * 9 * 64];
    __shared__ __align__(16) float Xsm[10 * 3 * 72];
    const int tid = threadIdx.x;
    const int tx = tid & 15, ty = tid >> 4;
    const int x0 = blockIdx.x * 64;
    const int yy = blockIdx.y;
    const int bz = blockIdx.z;
    const int b = bz >> 1, o0 = (bz & 1) * 64;
    const float* Xb = Xin + (size_t)b * PLANEP;

    unsigned long long acc2[2][4];
#pragma unroll
    for (int i = 0; i < 2; i++)
#pragma unroll
        for (int j = 0; j < 4; j++) acc2[i][j] = 0ull;

    for (int c0 = 0; c0 < 300; c0 += 10) {
        for (int idx = tid; idx < 5760; idx += 256) {
            int cc = idx / 576; int rem = idx - cc * 576;
            int tap = rem >> 6; int o = rem & 63;
            Ws[idx] = g_Wc[((size_t)(c0 + cc) * 9 + tap) * 128 + o0 + o];
        }
        for (int idx = tid; idx < 1980; idx += 256) {
            int cc = idx / 198; int rem = idx - cc * 198;
            int r = rem / 66; int col = rem - r * 66;
            int gx = x0 + col;
            float v = (gx < 144) ? Xb[(size_t)(c0 + cc) * HWN + (yy + r) * 144 + gx] : 0.f;
            Xsm[(cc * 3 + r) * 72 + col] = v;
        }
        __syncthreads();
#pragma unroll
        for (int cc = 0; cc < 10; cc++) {
            unsigned long long xd[3][6];
#pragma unroll
            for (int r = 0; r < 3; r++) {
                const float* xp = Xsm + (cc * 3 + r) * 72 + tx * 4;
                float4 v4 = *(const float4*)xp;
                xd[r][0] = dup2(v4.x); xd[r][1] = dup2(v4.y);
                xd[r][2] = dup2(v4.z); xd[r][3] = dup2(v4.w);
                xd[r][4] = dup2(xp[4]); xd[r][5] = dup2(xp[5]);
            }
#pragma unroll
            for (int tap = 0; tap < 9; tap++) {
                int dy = tap / 3, dx = tap - dy * 3;
                ulonglong2 wv = *(const ulonglong2*)(Ws + (cc * 9 + tap) * 64 + ty * 4);
#pragma unroll
                for (int j = 0; j < 4; j++) {
                    fma2(acc2[0][j], wv.x, xd[dy][j + dx]);
                    fma2(acc2[1][j], wv.y, xd[dy][j + dx]);
                }
            }
        }
        __syncthreads();
    }
#pragma unroll
    for (int ip = 0; ip < 2; ip++) {
        float2 v[4];
#pragma unroll
        for (int j = 0; j < 4; j++) v[j] = unp(acc2[ip][j]);
#pragma unroll
        for (int h = 0; h < 2; h++) {
            int o = o0 + ty * 4 + 2 * ip + h;
            float bv = bias[o];
            size_t rowbase = ((size_t)b * 128 + o) * HW2 + (size_t)yy * 142;
#pragma unroll
            for (int j = 0; j < 4; j++) {
                int xx = x0 + tx * 4 + j;
                if (xx < 142) H1[rowbase + xx] = gelu_f((h ? v[j].y : v[j].x) + bv);
            }
        }
    }
}

// ---------------- small kernels ----------------
__global__ void init_state(const float* __restrict__ Y6_, float* __restrict__ C12, float* __restrict__ X12)
{
    size_t i = (size_t)blockIdx.x * 256 + threadIdx.x;
    if (i >= (size_t)NB * PLANE) return;
    size_t b = i / PLANE, r = i - b * PLANE;
    size_t ybase = b * (size_t)6 * PLANE + r;
    float ye1 = Y6_[ybase + 0 * (size_t)PLANE];
    float yi1 = Y6_[ybase + 3 * (size_t)PLANE];
    float c = sigm(yi1) * (-ye1);
    size_t o = b * (size_t)PLANEP + r;
    C12[o] = c;
    X12[o] = fmaxf(c, 0.f);
}

__global__ void finalk(const float* __restrict__ H2, const float* __restrict__ w3,
                       const float* __restrict__ b3, float* __restrict__ out)
{
    __shared__ float ws[128];
    int tid = threadIdx.x;
    if (tid < 128) ws[tid] = w3[tid];
    __syncthreads();
    int b = blockIdx.y;
    int p = blockIdx.x * 256 + tid;
    if (p >= HW2) return;
    const float* hb = H2 + (size_t)b * 128 * HW2 + p;
    float acc = b3[0];
#pragma unroll 8
    for (int c = 0; c < 128; c++) acc += ws[c] * hb[(size_t)c * HW2];
    out[(size_t)b * HW2 + p] = acc;
}

// ---------------- fused weight/input prep (single launch) ----------------
struct PrepPtrs {
    const float* y;
    const float* ew[6];
    const float* eb[6];
    const float* dw[6];
    const float* lw1;
    const float* lw2;
};

#define N_WTD  (6*KPAD*KPAD)          // 614400
#define N_WTE  (ECH*1856)             // 118784
#define N_BE   1856
#define N_WC   (2700*128)             // 345600
#define N_WT2  (128*128)              // 16384
#define N_YP   (NB*ECH*HWN)           // 5308416
#define N_ZP   (2*NB*20*HWN)          // 3317760
#define N_PREP ((size_t)N_WTD+N_WTE+N_BE+N_WC+N_WT2+N_YP+N_ZP)

__global__ void prep_all(PrepPtrs P)
{
    size_t idx = (size_t)blockIdx.x * 256 + threadIdx.x;
    if (idx < N_WTD) {
        int g = (int)(idx / (KPAD * KPAD));
        int rem = (int)(idx - (size_t)g * KPAD * KPAD);
        int k = rem / KPAD, m = rem - k * KPAD;
        g_WtD[idx] = (k < 300 && m < 300) ? P.dw[g][m * 300 + k] : 0.f;
        return;
    }
    idx -= N_WTD;
    if (idx < N_WTE) {
        int k = (int)(idx / 1856), col = (int)(idx % 1856);
        float v = 0.f;
        if (k < 21 && col < 1800) {
            int g = col / 300, o = col - g * 300;
            v = P.ew[g][o * 21 + k];
        }
        g_WtE[idx] = v;
        return;
    }
    idx -= N_WTE;
    if (idx < N_BE) {
        float v = 0.f;
        if (idx < 1800) {
            int g = (int)idx / 300, o = (int)idx - g * 300;
            v = P.eb[g][o];
        }
        g_bE[idx] = v;
        return;
    }
    idx -= N_BE;
    if (idx < N_WC) {
        int tc = (int)(idx >> 7);
        int o  = (int)(idx & 127);
        g_Wc[idx] = P.lw1[(size_t)o * 2700 + tc];
        return;
    }
    idx -= N_WC;
    if (idx < N_WT2) {
        int k = (int)(idx >> 7), m = (int)(idx & 127);
        g_Wt2[idx] = P.lw2[m * 128 + k];
        return;
    }
    idx -= N_WT2;
    if (idx < N_YP) {
        int b = (int)(idx / (ECH * HWN));
        int rem = (int)(idx - (size_t)b * ECH * HWN);
        int k = rem / HWN;
        int p = rem - k * HWN;
        g_Ypad[idx] = (k < 21) ? P.y[((size_t)b * 21 + k) * HWN + p] : 0.f;
        return;
    }
    idx -= N_YP;
    if (idx < N_ZP) {
        // zero pad rows k in [300,320) of X12 and XT1 so GEMM never reads NaN garbage
        int w = (int)(idx / ((size_t)NB * 20 * HWN));
        size_t rem = idx - (size_t)w * NB * 20 * HWN;
        int b = (int)(rem / (20 * HWN));
        int rr = (int)(rem - (size_t)b * 20 * HWN);
        int row = rr / HWN, p = rr - row * HWN;
        float* dst = w ? g_XT1 : g_X12;
        dst[(size_t)b * PLANEP + (size_t)(300 + row) * HWN + p] = 0.f;
    }
}

// ---------------- launch ----------------
extern "C" void kernel_launch(void* const* d_in, const int* in_sizes, int n_in,
                              void* d_out, int out_size)
{
    (void)in_sizes; (void)n_in; (void)out_size;
    const float* y = (const float*)d_in[0];
    const float* ew[6] = {(const float*)d_in[1], (const float*)d_in[3], (const float*)d_in[5],
                          (const float*)d_in[7], (const float*)d_in[9], (const float*)d_in[11]};
    const float* eb[6] = {(const float*)d_in[2], (const float*)d_in[4], (const float*)d_in[6],
                          (const float*)d_in[8], (const float*)d_in[10], (const float*)d_in[12]};
    const float* dw[6] = {(const float*)d_in[13], (const float*)d_in[15], (const float*)d_in[17],
                          (const float*)d_in[19], (const float*)d_in[21], (const float*)d_in[23]};
    const float* db[6] = {(const float*)d_in[14], (const float*)d_in[16], (const float*)d_in[18],
                          (const float*)d_in[20], (const float*)d_in[22], (const float*)d_in[24]};
    const float* lw1 = (const float*)d_in[25];
    const float* lb1 = (const float*)d_in[26];
    const float* lw2 = (const float*)d_in[27];
    const float* lb2 = (const float*)d_in[28];
    const float* lw3 = (const float*)d_in[29];
    const float* lb3 = (const float*)d_in[30];
    float* out = (float*)d_out;

    float *Y6, *C12, *X12, *XT1, *CT1, *G0, *G1, *Ypad, *WtD, *WtE, *bE, *Wt2, *h1, *h2;
    cudaGetSymbolAddress((void**)&Y6,  g_Y6);
    cudaGetSymbolAddress((void**)&C12, g_C12);
    cudaGetSymbolAddress((void**)&X12, g_X12);
    cudaGetSymbolAddress((void**)&XT1, g_XT1);
    cudaGetSymbolAddress((void**)&CT1, g_CT1);
    cudaGetSymbolAddress((void**)&G0,  g_G0);
    cudaGetSymbolAddress((void**)&G1,  g_G1);
    cudaGetSymbolAddress((void**)&Ypad, g_Ypad);
    cudaGetSymbolAddress((void**)&WtD, g_WtD);
    cudaGetSymbolAddress((void**)&WtE, g_WtE);
    cudaGetSymbolAddress((void**)&bE,  g_bE);
    cudaGetSymbolAddress((void**)&Wt2, g_Wt2);
    cudaGetSymbolAddress((void**)&h1,  g_h1);
    cudaGetSymbolAddress((void**)&h2,  g_h2);

    // ---- launch 0: all prep in one kernel ----
    PrepPtrs P;
    P.y = y; P.lw1 = lw1; P.lw2 = lw2;
    for (int i = 0; i < 6; i++) { P.ew[i] = ew[i]; P.eb[i] = eb[i]; P.dw[i] = dw[i]; }
    prep_all<<<(int)((N_PREP + 255) / 256), 256>>>(P);

    // ---- launch 1: encoder, all 6 gconv(y,...) in one GEMM (M=1800, K=64 padded) ----
    gemm_tile<0, 16><<<dim3(162, 15, NB), 256>>>(WtE, bE, Ypad, Y6,
        ECH, 1800, 1856, HWN, (size_t)ECH * HWN, (size_t)6 * PLANE, 14,
        nullptr, nullptr, nullptr, nullptr, nullptr, 0, nullptr, nullptr, nullptr);

    // ---- launch 2 ----
    init_state<<<(int)(((size_t)NB * PLANE + 255) / 256), 256>>>(Y6, C12, X12);

    const float* YE1 = Y6;
    const float* YE2 = Y6 + (size_t)PLANE;
    const float* YF1 = Y6 + 2 * (size_t)PLANE;
    const float* YI1 = Y6 + 3 * (size_t)PLANE;
    const float* YF2 = Y6 + 4 * (size_t)PLANE;
    const float* YI2 = Y6 + 5 * (size_t)PLANE;
    const float* Wd1  = WtD + 0 * (KPAD * KPAD);
    const float* Wd2  = WtD + 1 * (KPAD * KPAD);
    const float* Wfx1 = WtD + 2 * (KPAD * KPAD);
    const float* Wix1 = WtD + 3 * (KPAD * KPAD);
    const float* Wfx2 = WtD + 4 * (KPAD * KPAD);
    const float* Wix2 = WtD + 5 * (KPAD * KPAD);

    dim3 gD(162, 3, NB);
    const size_t PP = PLANEP, Y6S = (size_t)6 * PLANE;

    for (int t = 0; t < 4; t++) {
        // step2: gates on X12, combine into CT1 / XT1
        gemm_tile<0, 16><<<gD, 256>>>(Wd2, db[1], X12, G0,
            KPAD, 300, KPAD, HWN, PP, PP, 2,
            nullptr, nullptr, nullptr, nullptr, nullptr, 0, nullptr, nullptr, nullptr);
        gemm_tile<0, 16><<<gD, 256>>>(Wfx2, db[4], X12, G1,
            KPAD, 300, KPAD, HWN, PP, PP, 2,
            nullptr, nullptr, nullptr, nullptr, nullptr, 0, nullptr, nullptr, nullptr);
        gemm_tile<1, 16><<<gD, 256>>>(Wix2, db[5], X12, CT1,
            KPAD, 300, KPAD, HWN, PP, PP, 2,
            G0, G1, YE2, YF2, YI2, Y6S, C12, (t == 0 ? nullptr : XT1), XT1);
        if (t < 3) {
            // step1: gates on XT1, combine into C12 / X12
            gemm_tile<0, 16><<<gD, 256>>>(Wd1, db[0], XT1, G0,
                KPAD, 300, KPAD, HWN, PP, PP, 2,
                nullptr, nullptr, nullptr, nullptr, nullptr, 0, nullptr, nullptr, nullptr);
            gemm_tile<0, 16><<<gD, 256>>>(Wfx1, db[2], XT1, G1,
                KPAD, 300, KPAD, HWN, PP, PP, 2,
                nullptr, nullptr, nullptr, nullptr, nullptr, 0, nullptr, nullptr, nullptr);
            gemm_tile<1, 16><<<gD, 256>>>(Wix1, db[3], XT1, C12,
                KPAD, 300, KPAD, HWN, PP, PP, 2,
                G0, G1, YE1, YF1, YI1, Y6S, CT1, XT1, X12);
        }
    }

    // ---- head ----
    conv3<<<dim3(3, 142, NB * 2), 256>>>(XT1, lb1, h1);
    gemm_tile<0, 16><<<dim3(158, 1, NB), 256>>>(Wt2, lb2, h1, h2,
        128, 128, 128, HW2, (size_t)128 * HW2, (size_t)128 * HW2, 1,
        nullptr, nullptr, nullptr, nullptr, nullptr, 0, nullptr, nullptr, nullptr);
    finalk<<<dim3((HW2 + 255) / 256, NB), 256>>>(h2, lw3, lb3, out);
}

// round 16
// speedup vs baseline: 1.0015x; 1.0015x over previous
#include <cuda_runtime.h>
#include <math.h>
#include <stdint.h>

// ---------------- problem constants ----------------
#define HWN    20736               // 144*144
#define NB     4
#define DDIM   300
#define KPAD   320                 // K padded for BK=16 pipeline
#define PLANE  (DDIM*HWN)          // 6,220,800  (Y6 row stride region)
#define PLANEP (KPAD*HWN)          // 6,635,520  (padded activation plane)
#define HW2    20164               // 142*142
#define ECH    64                  // encoder channels padded 21 -> 64

// ---------------- static device scratch ----------------
__device__ float g_Y6 [(size_t)NB*6*PLANE];
__device__ float g_C12[(size_t)NB*PLANEP];
__device__ float g_X12[(size_t)NB*PLANEP];
__device__ float g_XT1[(size_t)NB*PLANEP];
__device__ float g_CT1[(size_t)NB*PLANEP];
__device__ float g_G0 [(size_t)NB*PLANEP];
__device__ float g_G1 [(size_t)NB*PLANEP];
__device__ float g_Ypad[(size_t)NB*ECH*HWN];    // y zero-padded 21->64 channels
__device__ float g_WtD[6*KPAD*KPAD];            // 6 D weights, [g][k<320][m<320], zero pads
__device__ float g_WtE[ECH*1856];               // stacked encoder weights, transposed, zero pads
__device__ float g_bE [1856];
__device__ float g_Wc [2700*128];               // conv weights [(c*9+tap)][o]
__device__ float g_Wt2[128*128];                // line_w2 transposed
__device__ float g_h1[(size_t)NB*128*HW2];
__device__ float g_h2[(size_t)NB*128*HW2];

// ---------------- helpers ----------------
__device__ __forceinline__ float gelu_f(float x) {
    return 0.5f * x * (1.0f + erff(x * 0.7071067811865475f));
}
__device__ __forceinline__ float sigm(float x) { return 1.0f / (1.0f + expf(-x)); }

__device__ __forceinline__ unsigned long long dup2(float x) {
    unsigned long long r;
    asm("mov.b64 %0, {%1, %1};" : "=l"(r) : "f"(x));
    return r;
}
__device__ __forceinline__ void fma2(unsigned long long &d, unsigned long long a, unsigned long long b) {
    asm("fma.rn.f32x2 %0, %1, %2, %0;" : "+l"(d) : "l"(a), "l"(b));
}
__device__ __forceinline__ float2 unp(unsigned long long v) {
    float2 r;
    asm("mov.b64 {%0, %1}, %2;" : "=f"(r.x), "=f"(r.y) : "l"(v));
    return r;
}

#define CP_COMMIT()  asm volatile("cp.async.commit_group;" ::: "memory")
#define CP_WAIT(n)   asm volatile("cp.async.wait_group %0;" :: "n"(n) : "memory")

__device__ __forceinline__ void cpa16(uint32_t dst, const float* src) {
    asm volatile("cp.async.ca.shared.global [%0], [%1], 16;" :: "r"(dst), "l"(src) : "memory");
}
__device__ __forceinline__ void cpa4(uint32_t dst, const float* src) {
    asm volatile("cp.async.ca.shared.global [%0], [%1], 4;" :: "r"(dst), "l"(src) : "memory");
}
__device__ __forceinline__ void sts0(uint32_t dst) {
    asm volatile("st.shared.u32 [%0], %1;" :: "r"(dst), "r"(0u) : "memory");
}

// ---------------- cp.async stage loader ----------------
// A tile: BK x TM from Wt (K padded: no k predicate, Mpad covers m range).
// X tile: BK x 128 from Xb (predicated on N only; K padded rows exist in buffers).
template<int BK, int TM>
__device__ __forceinline__ void stage_issue(
    uint32_t sA, uint32_t sX,
    const float* __restrict__ Wt, const float* __restrict__ Xb,
    int k0, int m0, int p0, int Mpad, int N)
{
    const int tid = threadIdx.x;
    constexpr int ACH = BK * TM / 1024;     // 16B chunks per thread
#pragma unroll
    for (int i = 0; i < ACH; i++) {
        int off = (tid + i * 256) * 4;
        int kk = off / TM, mm = off % TM;
        cpa16(sA + off * 4, Wt + (size_t)(k0 + kk) * Mpad + m0 + mm);
    }
    constexpr int XCH = BK * 128 / 1024;
#pragma unroll
    for (int i = 0; i < XCH; i++) {
        int off = (tid + i * 256) * 4;
        int kk = off >> 7, pp = p0 + (off & 127);
        const float* src = Xb + (size_t)(k0 + kk) * N + pp;
        uint32_t dst = sX + off * 4;
        if (pp + 3 < N) {
            cpa16(dst, src);
        } else {
#pragma unroll
            for (int e = 0; e < 4; e++) {
                if (pp + e < N) cpa4(dst + e * 4, src + e);
                else            sts0(dst + e * 4);
            }
        }
    }
}

// ---------------- GEMM body: 128-wide N tile, TM = 16*MT wide M tile ----------------
// MODE 0: O = gelu(acc + bias)
// MODE 1: fused gate combine (this GEMM is the 'wix' gate):
//   gi=gelu(acc+bias); it=sigm(gi+Yi); ft=sigm(G1+Yf); ctl=Ya+S2-G0;
//   ct=S1*ft+ctl*it; O=ct; O2=relu(ct)
template<int MODE, int BK, int MT>
__device__ __forceinline__ void gemm_body(
    const float* __restrict__ Wt, const float* __restrict__ bias,
    const float* __restrict__ X, float* O,
    int K, int M, int Mpad, int N, size_t bsX, size_t bsO,
    const float* __restrict__ G0p, const float* __restrict__ G1p,
    const float* __restrict__ Ya, const float* __restrict__ Yf, const float* __restrict__ Yi,
    size_t bsY, const float* __restrict__ S1, const float* __restrict__ S2, float* O2,
    float* AsBuf, float* XsBuf, int m0)
{
    constexpr int TM = 16 * MT;
    constexpr int MP = MT / 2;
    constexpr int STG = BK * 128;           // floats per stage buffer
    const int tid = threadIdx.x;
    const int tx = tid & 15, ty = tid >> 4;
    const int p0 = blockIdx.x * 128;
    const int b  = blockIdx.z;
    const float* Xb = X + (size_t)b * bsX;

    uint32_t aAddr = (uint32_t)__cvta_generic_to_shared(AsBuf);
    uint32_t xAddr = (uint32_t)__cvta_generic_to_shared(XsBuf);

    unsigned long long acc2[MP][8];
#pragma unroll
    for (int i = 0; i < MP; i++)
#pragma unroll
        for (int j = 0; j < 8; j++) acc2[i][j] = 0ull;

    stage_issue<BK, TM>(aAddr, xAddr, Wt, Xb, 0, m0, p0, Mpad, N);
    CP_COMMIT();

    int buf = 0;
    for (int k0 = 0; k0 < K; k0 += BK) {
        if (k0 + BK < K) {
            int nb = buf ^ 1;
            stage_issue<BK, TM>(aAddr + nb * STG * 4, xAddr + nb * STG * 4,
                                Wt, Xb, k0 + BK, m0, p0, Mpad, N);
            CP_COMMIT();
            CP_WAIT(1);
        } else {
            CP_WAIT(0);
        }
        __syncthreads();
        const float* As = AsBuf + buf * STG;
        const float* Xs = XsBuf + buf * STG;
#pragma unroll
        for (int kk = 0; kk < BK; kk++) {
            unsigned long long a2[MP];
            const float* ab = As + kk * TM + ty * MT;
            if (MT == 8) {
                ulonglong2 v0 = *(const ulonglong2*)ab;
                ulonglong2 v1 = *(const ulonglong2*)(ab + 4);
                a2[0] = v0.x; a2[1] = v0.y;
                if (MP > 2) { a2[2] = v1.x; a2[3] = v1.y; }
            } else {
                ulonglong2 v0 = *(const ulonglong2*)ab;
                a2[0] = v0.x; a2[1] = v0.y;
            }
            float4 xa = *(const float4*)(Xs + kk * 128 + tx * 4);
            float4 xb = *(const float4*)(Xs + kk * 128 + 64 + tx * 4);
            unsigned long long xd[8] = {dup2(xa.x), dup2(xa.y), dup2(xa.z), dup2(xa.w),
                                        dup2(xb.x), dup2(xb.y), dup2(xb.z), dup2(xb.w)};
#pragma unroll
            for (int ip = 0; ip < MP; ip++)
#pragma unroll
                for (int j = 0; j < 8; j++) fma2(acc2[ip][j], a2[ip], xd[j]);
        }
        __syncthreads();
        buf ^= 1;
    }

    const int pA = p0 + tx * 4;
    const int pB = p0 + 64 + tx * 4;

    if (MODE == 0) {
#pragma unroll
        for (int ip = 0; ip < MP; ip++) {
            float2 v[8];
#pragma unroll
            for (int j = 0; j < 8; j++) v[j] = unp(acc2[ip][j]);
#pragma unroll
            for (int h = 0; h < 2; h++) {
                int o = m0 + ty * MT + 2 * ip + h;
                if (o >= M) continue;
                float bv = bias[o];
                size_t row = (size_t)b * bsO + (size_t)o * N;
                float r[8];
#pragma unroll
                for (int j = 0; j < 8; j++) r[j] = gelu_f((h ? v[j].y : v[j].x) + bv);
                if (pA + 3 < N) {
                    float4 st; st.x = r[0]; st.y = r[1]; st.z = r[2]; st.w = r[3];
                    *(float4*)(O + row + pA) = st;
                } else {
#pragma unroll
                    for (int e = 0; e < 4; e++) if (pA + e < N) O[row + pA + e] = r[e];
                }
                if (pB + 3 < N) {
                    float4 st; st.x = r[4]; st.y = r[5]; st.z = r[6]; st.w = r[7];
                    *(float4*)(O + row + pB) = st;
                } else {
#pragma unroll
                    for (int e = 0; e < 4; e++) if (pB + e < N) O[row + pB + e] = r[4 + e];
                }
            }
        }
    } else {
        // only used with N multiple of 128 (full tiles)
#pragma unroll
        for (int ip = 0; ip < MP; ip++) {
            float2 v[8];
#pragma unroll
            for (int j = 0; j < 8; j++) v[j] = unp(acc2[ip][j]);
#pragma unroll
            for (int h = 0; h < 2; h++) {
                int o = m0 + ty * MT + 2 * ip + h;
                if (o >= M) continue;
                float bv = bias[o];
                size_t rO = (size_t)b * bsO + (size_t)o * N;
                size_t rY = (size_t)b * bsY + (size_t)o * N;
#pragma unroll
                for (int g = 0; g < 2; g++) {
                    int pc = g ? pB : pA;
                    float G0a[4], G1a[4], YAa[4], YFa[4], YIa[4], S1a[4], S2a[4];
                    *(float4*)G0a = *(const float4*)(G0p + rO + pc);
                    *(float4*)G1a = *(const float4*)(G1p + rO + pc);
                    *(float4*)YAa = *(const float4*)(Ya + rY + pc);
                    *(float4*)YFa = *(const float4*)(Yf + rY + pc);
                    *(float4*)YIa = *(const float4*)(Yi + rY + pc);
                    *(float4*)S1a = *(const float4*)(S1 + rO + pc);
                    if (S2) { *(float4*)S2a = *(const float4*)(S2 + rO + pc); }
                    else    { S2a[0] = S2a[1] = S2a[2] = S2a[3] = 0.f; }
                    float ct[4], xt[4];
#pragma unroll
                    for (int j = 0; j < 4; j++) {
                        float accv = h ? v[4 * g + j].y : v[4 * g + j].x;
                        float gi  = gelu_f(accv + bv);
                        float it  = sigm(gi + YIa[j]);
                        float ft  = sigm(G1a[j] + YFa[j]);
                        float ctl = YAa[j] + S2a[j] - G0a[j];
                        ct[j] = S1a[j] * ft + ctl * it;
                        xt[j] = fmaxf(ct[j], 0.f);
                    }
                    float4 c4; c4.x = ct[0]; c4.y = ct[1]; c4.z = ct[2]; c4.w = ct[3];
                    float4 x4; x4.x = xt[0]; x4.y = xt[1]; x4.z = xt[2]; x4.w = xt[3];
                    *(float4*)(O  + rO + pc) = c4;
                    *(float4*)(O2 + rO + pc) = x4;
                }
            }
        }
    }
}

template<int MODE, int BK>
__global__ void __launch_bounds__(256, 2) gemm_tile(
    const float* __restrict__ Wt, const float* __restrict__ bias,
    const float* __restrict__ X, float* O,
    int K, int M, int Mpad, int N, size_t bsX, size_t bsO, int nFull,
    const float* G0p, const float* G1p,
    const float* Ya, const float* Yf, const float* Yi, size_t bsY,
    const float* S1, const float* S2, float* O2)
{
    __shared__ __align__(16) float As[2 * BK * 128];
    __shared__ __align__(16) float Xs[2 * BK * 128];
    if ((int)blockIdx.y < nFull)
        gemm_body<MODE, BK, 8>(Wt, bias, X, O, K, M, Mpad, N, bsX, bsO,
                               G0p, G1p, Ya, Yf, Yi, bsY, S1, S2, O2,
                               As, Xs, (int)blockIdx.y * 128);
    else
        gemm_body<MODE, BK, 4>(Wt, bias, X, O, K, M, Mpad, N, bsX, bsO,
                               G0p, G1p, Ya, Yf, Yi, bsY, S1, S2, O2,
                               As, Xs, nFull * 128 + ((int)blockIdx.y - nFull) * 64);
}

// ---------------- 3x3 valid conv 300->128, + gelu (f32x2) ----------------
__global__ void __launch_bounds__(256) conv3(const float* __restrict__ Xin,
                                             const float* __restrict__ bias,
                                             float* __restrict__ H1)
{
    __shared__ __align__(16) float Ws[10 * 9 * 64];
    __shared__ __align__(16) float Xsm[10 * 3 * 72];
    const int tid = threadIdx.x;
    const int tx = tid & 15, ty = tid >> 4;
    const int x0 = blockIdx.x * 64;
    const int yy = blockIdx.y;
    const int bz = blockIdx.z;
    const int b = bz >> 1, o0 = (bz & 1) * 64;
    const float* Xb = Xin + (size_t)b * PLANEP;

    unsigned long long acc2[2][4];
#pragma unroll
    for (int i = 0; i < 2; i++)
#pragma unroll
        for (int j = 0; j < 4; j++) acc2[i][j] = 0ull;

    for (int c0 = 0; c0 < 300; c0 += 10) {
        for (int idx = tid; idx < 5760; idx += 256) {
            int cc = idx / 576; int rem = idx - cc * 576;
            int tap = rem >> 6; int o = rem & 63;
            Ws[idx] = g_Wc[((size_t)(c0 + cc) * 9 + tap) * 128 + o0 + o];
        }
        for (int idx = tid; idx < 1980; idx += 256) {
            int cc = idx / 198; int rem = idx - cc * 198;
            int r = rem / 66; int col = rem - r * 66;
            int gx = x0 + col;
            float v = (gx < 144) ? Xb[(size_t)(c0 + cc) * HWN + (yy + r) * 144 + gx] : 0.f;
            Xsm[(cc * 3 + r) * 72 + col] = v;
        }
        __syncthreads();
#pragma unroll
        for (int cc = 0; cc < 10; cc++) {
            unsigned long long xd[3][6];
#pragma unroll
            for (int r = 0; r < 3; r++) {
                const float* xp = Xsm + (cc * 3 + r) * 72 + tx * 4;
                float4 v4 = *(const float4*)xp;
                xd[r][0] = dup2(v4.x); xd[r][1] = dup2(v4.y);
                xd[r][2] = dup2(v4.z); xd[r][3] = dup2(v4.w);
                xd[r][4] = dup2(xp[4]); xd[r][5] = dup2(xp[5]);
            }
#pragma unroll
            for (int tap = 0; tap < 9; tap++) {
                int dy = tap / 3, dx = tap - dy * 3;
                ulonglong2 wv = *(const ulonglong2*)(Ws + (cc * 9 + tap) * 64 + ty * 4);
#pragma unroll
                for (int j = 0; j < 4; j++) {
                    fma2(acc2[0][j], wv.x, xd[dy][j + dx]);
                    fma2(acc2[1][j], wv.y, xd[dy][j + dx]);
                }
            }
        }
        __syncthreads();
    }
#pragma unroll
    for (int ip = 0; ip < 2; ip++) {
        float2 v[4];
#pragma unroll
        for (int j = 0; j < 4; j++) v[j] = unp(acc2[ip][j]);
#pragma unroll
        for (int h = 0; h < 2; h++) {
            int o = o0 + ty * 4 + 2 * ip + h;
            float bv = bias[o];
            size_t rowbase = ((size_t)b * 128 + o) * HW2 + (size_t)yy * 142;
#pragma unroll
            for (int j = 0; j < 4; j++) {
                int xx = x0 + tx * 4 + j;
                if (xx < 142) H1[rowbase + xx] = gelu_f((h ? v[j].y : v[j].x) + bv);
            }
        }
    }
}

// ---------------- small kernels ----------------
__global__ void init_state(const float* __restrict__ Y6_, float* __restrict__ C12, float* __restrict__ X12)
{
    size_t i = (size_t)blockIdx.x * 256 + threadIdx.x;
    if (i >= (size_t)NB * PLANE) return;
    size_t b = i / PLANE, r = i - b * PLANE;
    size_t ybase = b * (size_t)6 * PLANE + r;
    float ye1 = Y6_[ybase + 0 * (size_t)PLANE];
    float yi1 = Y6_[ybase + 3 * (size_t)PLANE];
    float c = sigm(yi1) * (-ye1);
    size_t o = b * (size_t)PLANEP + r;
    C12[o] = c;
    X12[o] = fmaxf(c, 0.f);
}

__global__ void finalk(const float* __restrict__ H2, const float* __restrict__ w3,
                       const float* __restrict__ b3, float* __restrict__ out)
{
    __shared__ float ws[128];
    int tid = threadIdx.x;
    if (tid < 128) ws[tid] = w3[tid];
    __syncthreads();
    int b = blockIdx.y;
    int p = blockIdx.x * 256 + tid;
    if (p >= HW2) return;
    const float* hb = H2 + (size_t)b * 128 * HW2 + p;
    float acc = b3[0];
#pragma unroll 8
    for (int c = 0; c < 128; c++) acc += ws[c] * hb[(size_t)c * HW2];
    out[(size_t)b * HW2 + p] = acc;
}

// ---------------- fused weight/input prep (single launch) ----------------
struct PrepPtrs {
    const float* y;
    const float* ew[6];
    const float* eb[6];
    const float* dw[6];
    const float* lw1;
    const float* lw2;
};

#define N_WTD  (6*KPAD*KPAD)          // 614400
#define N_WTE  (ECH*1856)             // 118784
#define N_BE   1856
#define N_WC   (2700*128)             // 345600
#define N_WT2  (128*128)              // 16384
#define N_YP   (NB*ECH*HWN)           // 5308416
#define N_ZP   (2*NB*20*HWN)          // 3317760
#define N_PREP ((size_t)N_WTD+N_WTE+N_BE+N_WC+N_WT2+N_YP+N_ZP)

__global__ void prep_all(PrepPtrs P)
{
    size_t idx = (size_t)blockIdx.x * 256 + threadIdx.x;
    if (idx < N_WTD) {
        int g = (int)(idx / (KPAD * KPAD));
        int rem = (int)(idx - (size_t)g * KPAD * KPAD);
        int k = rem / KPAD, m = rem - k * KPAD;
        g_WtD[idx] = (k < 300 && m < 300) ? P.dw[g][m * 300 + k] : 0.f;
        return;
    }
    idx -= N_WTD;
    if (idx < N_WTE) {
        int k = (int)(idx / 1856), col = (int)(idx % 1856);
        float v = 0.f;
        if (k < 21 && col < 1800) {
            int g = col / 300, o = col - g * 300;
            v = P.ew[g][o * 21 + k];
        }
        g_WtE[idx] = v;
        return;
    }
    idx -= N_WTE;
    if (idx < N_BE) {
        float v = 0.f;
        if (idx < 1800) {
            int g = (int)idx / 300, o = (int)idx - g * 300;
            v = P.eb[g][o];
        }
        g_bE[idx] = v;
        return;
    }
    idx -= N_BE;
    if (idx < N_WC) {
        int tc = (int)(idx >> 7);
        int o  = (int)(idx & 127);
        g_Wc[idx] = P.lw1[(size_t)o * 2700 + tc];
        return;
    }
    idx -= N_WC;
    if (idx < N_WT2) {
        int k = (int)(idx >> 7), m = (int)(idx & 127);
        g_Wt2[idx] = P.lw2[m * 128 + k];
        return;
    }
    idx -= N_WT2;
    if (idx < N_YP) {
        int b = (int)(idx / (ECH * HWN));
        int rem = (int)(idx - (size_t)b * ECH * HWN);
        int k = rem / HWN;
        int p = rem - k * HWN;
        g_Ypad[idx] = (k < 21) ? P.y[((size_t)b * 21 + k) * HWN + p] : 0.f;
        return;
    }
    idx -= N_YP;
    if (idx < N_ZP) {
        // zero pad rows k in [300,320) of X12 and XT1 so GEMM never reads NaN garbage
        int w = (int)(idx / ((size_t)NB * 20 * HWN));
        size_t rem = idx - (size_t)w * NB * 20 * HWN;
        int b = (int)(rem / (20 * HWN));
        int rr = (int)(rem - (size_t)b * 20 * HWN);
        int row = rr / HWN, p = rr - row * HWN;
        float* dst = w ? g_XT1 : g_X12;
        dst[(size_t)b * PLANEP + (size_t)(300 + row) * HWN + p] = 0.f;
    }
}

// ---------------- launch ----------------
extern "C" void kernel_launch(void* const* d_in, const int* in_sizes, int n_in,
                              void* d_out, int out_size)
{
    (void)in_sizes; (void)n_in; (void)out_size;
    const float* y = (const float*)d_in[0];
    const float* ew[6] = {(const float*)d_in[1], (const float*)d_in[3], (const float*)d_in[5],
                          (const float*)d_in[7], (const float*)d_in[9], (const float*)d_in[11]};
    const float* eb[6] = {(const float*)d_in[2], (const float*)d_in[4], (const float*)d_in[6],
                          (const float*)d_in[8], (const float*)d_in[10], (const float*)d_in[12]};
    const float* dw[6] = {(const float*)d_in[13], (const float*)d_in[15], (const float*)d_in[17],
                          (const float*)d_in[19], (const float*)d_in[21], (const float*)d_in[23]};
    const float* db[6] = {(const float*)d_in[14], (const float*)d_in[16], (const float*)d_in[18],
                          (const float*)d_in[20], (const float*)d_in[22], (const float*)d_in[24]};
    const float* lw1 = (const float*)d_in[25];
    const float* lb1 = (const float*)d_in[26];
    const float* lw2 = (const float*)d_in[27];
    const float* lb2 = (const float*)d_in[28];
    const float* lw3 = (const float*)d_in[29];
    const float* lb3 = (const float*)d_in[30];
    float* out = (float*)d_out;

    float *Y6, *C12, *X12, *XT1, *CT1, *G0, *G1, *Ypad, *WtD, *WtE, *bE, *Wt2, *h1, *h2;
    cudaGetSymbolAddress((void**)&Y6,  g_Y6);
    cudaGetSymbolAddress((void**)&C12, g_C12);
    cudaGetSymbolAddress((void**)&X12, g_X12);
    cudaGetSymbolAddress((void**)&XT1, g_XT1);
    cudaGetSymbolAddress((void**)&CT1, g_CT1);
    cudaGetSymbolAddress((void**)&G0,  g_G0);
    cudaGetSymbolAddress((void**)&G1,  g_G1);
    cudaGetSymbolAddress((void**)&Ypad, g_Ypad);
    cudaGetSymbolAddress((void**)&WtD, g_WtD);
    cudaGetSymbolAddress((void**)&WtE, g_WtE);
    cudaGetSymbolAddress((void**)&bE,  g_bE);
    cudaGetSymbolAddress((void**)&Wt2, g_Wt2);
    cudaGetSymbolAddress((void**)&h1,  g_h1);
    cudaGetSymbolAddress((void**)&h2,  g_h2);

    // ---- launch 0: all prep in one kernel ----
    PrepPtrs P;
    P.y = y; P.lw1 = lw1; P.lw2 = lw2;
    for (int i = 0; i < 6; i++) { P.ew[i] = ew[i]; P.eb[i] = eb[i]; P.dw[i] = dw[i]; }
    prep_all<<<(int)((N_PREP + 255) / 256), 256>>>(P);

    // ---- launch 1: encoder, all 6 gconv(y,...) in one GEMM (M=1800, K=64 padded) ----
    gemm_tile<0, 16><<<dim3(162, 15, NB), 256>>>(WtE, bE, Ypad, Y6,
        ECH, 1800, 1856, HWN, (size_t)ECH * HWN, (size_t)6 * PLANE, 14,
        nullptr, nullptr, nullptr, nullptr, nullptr, 0, nullptr, nullptr, nullptr);

    // ---- launch 2 ----
    init_state<<<(int)(((size_t)NB * PLANE + 255) / 256), 256>>>(Y6, C12, X12);

    const float* YE1 = Y6;
    const float* YE2 = Y6 + (size_t)PLANE;
    const float* YF1 = Y6 + 2 * (size_t)PLANE;
    const float* YI1 = Y6 + 3 * (size_t)PLANE;
    const float* YF2 = Y6 + 4 * (size_t)PLANE;
    const float* YI2 = Y6 + 5 * (size_t)PLANE;
    const float* Wd1  = WtD + 0 * (KPAD * KPAD);
    const float* Wd2  = WtD + 1 * (KPAD * KPAD);
    const float* Wfx1 = WtD + 2 * (KPAD * KPAD);
    const float* Wix1 = WtD + 3 * (KPAD * KPAD);
    const float* Wfx2 = WtD + 4 * (KPAD * KPAD);
    const float* Wix2 = WtD + 5 * (KPAD * KPAD);

    dim3 gD(162, 3, NB);
    const size_t PP = PLANEP, Y6S = (size_t)6 * PLANE;

    for (int t = 0; t < 4; t++) {
        // step2: gates on X12, combine into CT1 / XT1
        gemm_tile<0, 16><<<gD, 256>>>(Wd2, db[1], X12, G0,
            KPAD, 300, KPAD, HWN, PP, PP, 2,
            nullptr, nullptr, nullptr, nullptr, nullptr, 0, nullptr, nullptr, nullptr);
        gemm_tile<0, 16><<<gD, 256>>>(Wfx2, db[4], X12, G1,
            KPAD, 300, KPAD, HWN, PP, PP, 2,
            nullptr, nullptr, nullptr, nullptr, nullptr, 0, nullptr, nullptr, nullptr);
        gemm_tile<1, 16><<<gD, 256>>>(Wix2, db[5], X12, CT1,
            KPAD, 300, KPAD, HWN, PP, PP, 2,
            G0, G1, YE2, YF2, YI2, Y6S, C12, (t == 0 ? nullptr : XT1), XT1);
        if (t < 3) {
            // step1: gates on XT1, combine into C12 / X12
            gemm_tile<0, 16><<<gD, 256>>>(Wd1, db[0], XT1, G0,
                KPAD, 300, KPAD, HWN, PP, PP, 2,
                nullptr, nullptr, nullptr, nullptr, nullptr, 0, nullptr, nullptr, nullptr);
            gemm_tile<0, 16><<<gD, 256>>>(Wfx1, db[2], XT1, G1,
                KPAD, 300, KPAD, HWN, PP, PP, 2,
                nullptr, nullptr, nullptr, nullptr, nullptr, 0, nullptr, nullptr, nullptr);
            gemm_tile<1, 16><<<gD, 256>>>(Wix1, db[3], XT1, C12,
                KPAD, 300, KPAD, HWN, PP, PP, 2,
                G0, G1, YE1, YF1, YI1, Y6S, CT1, XT1, X12);
        }
    }

    // ---- head ----
    conv3<<<dim3(3, 142, NB * 2), 256>>>(XT1, lb1, h1);
    gemm_tile<0, 16><<<dim3(158, 1, NB), 256>>>(Wt2, lb2, h1, h2,
        128, 128, 128, HW2, (size_t)128 * HW2, (size_t)128 * HW2, 1,
        nullptr, nullptr, nullptr, nullptr, nullptr, 0, nullptr, nullptr, nullptr);
    finalk<<<dim3((HW2 + 255) / 256, NB), 256>>>(h2, lw3, lb3, out);
}